// round 6
// baseline (speedup 1.0000x reference)
#include <cuda_runtime.h>
#include <cstdint>
#include <cstddef>

#define N_SEQ 8192
#define M_SEQ 8192
#define D_DIM 1024

__device__ float g_Q [(size_t)N_SEQ * D_DIM];
__device__ float g_K [(size_t)M_SEQ * D_DIM];
__device__ float g_Vt[(size_t)D_DIM * M_SEQ];
__device__ float g_S [(size_t)N_SEQ * M_SEQ];

#define DEV __device__ __forceinline__

DEV uint32_t smem_u32(const void* p) {
    uint32_t a;
    asm("{ .reg .u64 t; cvta.to.shared.u64 t, %1; cvt.u32.u64 %0, t; }"
        : "=r"(a) : "l"(p));
    return a;
}
DEV uint32_t f2t(float x) {   // fp32 -> tf32 RNA; dest must be .b32 reg
    uint32_t y;
    asm("cvt.rna.tf32.f32 %0, %1;" : "=r"(y) : "f"(x));
    return y;
}
DEV void cp_async16(uint32_t dst, const void* src) {
    asm volatile("cp.async.cg.shared.global [%0], [%1], 16;"
                 :: "r"(dst), "l"(src) : "memory");
}
#define CP_COMMIT() asm volatile("cp.async.commit_group;" ::: "memory")
#define CP_WAIT2()  asm volatile("cp.async.wait_group 2;" ::: "memory")

// swizzled smem address: row*128B + 16B-chunk (c>>2)^(row&7), word c&3
DEV uint32_t sw_addr(uint32_t base, int row, int col) {
    return base + (uint32_t)(row * 128) +
           ((uint32_t)(((col >> 2) ^ (row & 7)) << 4) | (uint32_t)((col & 3) << 2));
}
DEV uint32_t lds_tf32(uint32_t a) {
    float v;
    asm volatile("ld.shared.b32 %0, [%1];" : "=f"(v) : "r"(a));
    return f2t(v);
}
DEV void mma_op(float* c, const uint32_t* a, const uint32_t* b) {
    asm volatile(
        "mma.sync.aligned.m16n8k8.row.col.f32.tf32.tf32.f32 "
        "{%0,%1,%2,%3}, {%4,%5,%6,%7}, {%8,%9}, {%0,%1,%2,%3};"
        : "+f"(c[0]), "+f"(c[1]), "+f"(c[2]), "+f"(c[3])
        : "r"(a[0]), "r"(a[1]), "r"(a[2]), "r"(a[3]), "r"(b[0]), "r"(b[1]));
}

// ============================================================================
// C[M,N] = alpha * A[M,K] . B[N,K]^T (+bias).  A,B k-major fp32.
// grid = (M/128, N/128), 256 threads, 4-stage cp.async pipeline.
// bias_mode: 0 none, 1 per-column bias[n], 2 per-row bias[m]
// ============================================================================
#define STAGES 4
#define SMEM_BYTES (STAGES * 2 * 16384)

__global__ __launch_bounds__(256)
void gemm_tf32_kernel(const float* __restrict__ A, const float* __restrict__ B,
                      float* __restrict__ C, const float* __restrict__ bias,
                      int bias_mode, int K, int lda, int ldb, int ldc, float alpha)
{
    extern __shared__ char smem[];
    const uint32_t sA = smem_u32(smem);
    const uint32_t sB = sA + STAGES * 16384;

    const int tid  = threadIdx.x;
    const int lane = tid & 31, wid = tid >> 5;
    const int g = lane >> 2, tg = lane & 3;
    const int wm = wid & 1, wn = wid >> 1;        // warp tile: 64 x 32

    const float* Ab = A + (size_t)blockIdx.x * 128 * lda;
    const float* Bb = B + (size_t)blockIdx.y * 128 * ldb;
    const int niter = K >> 5;

    const int lr  = tid >> 3;                     // load row 0..31 (+32/pass)
    const int lc4 = tid & 7;                      // float4 col 0..7

    auto issue = [&](int stage, int kc) {
        const uint32_t dA = sA + stage * 16384;
        const uint32_t dB = sB + stage * 16384;
        #pragma unroll
        for (int p = 0; p < 4; ++p) {
            const int row = lr + p * 32;
            const uint32_t so = (uint32_t)(row * 128 + ((lc4 ^ (row & 7)) << 4));
            cp_async16(dA + so, Ab + (size_t)row * lda + kc * 32 + lc4 * 4);
            cp_async16(dB + so, Bb + (size_t)row * ldb + kc * 32 + lc4 * 4);
        }
    };

    issue(0, 0); CP_COMMIT();
    issue(1, 1); CP_COMMIT();
    issue(2, 2); CP_COMMIT();

    float acc[4][4][4] = {};

    for (int i = 0; i < niter; ++i) {
        CP_WAIT2();
        __syncthreads();
        if (i + 3 < niter) issue((i + 3) & 3, i + 3);
        CP_COMMIT();

        const uint32_t aB = sA + (i & 3) * 16384;
        const uint32_t bB = sB + (i & 3) * 16384;
        #pragma unroll
        for (int s = 0; s < 4; ++s) {
            uint32_t af[4][4];
            #pragma unroll
            for (int mi = 0; mi < 4; ++mi) {
                const int r0 = wm * 64 + mi * 16 + g;
                af[mi][0] = lds_tf32(sw_addr(aB, r0,     s * 8 + tg));
                af[mi][1] = lds_tf32(sw_addr(aB, r0 + 8, s * 8 + tg));
                af[mi][2] = lds_tf32(sw_addr(aB, r0,     s * 8 + tg + 4));
                af[mi][3] = lds_tf32(sw_addr(aB, r0 + 8, s * 8 + tg + 4));
            }
            uint32_t bf[4][2];
            #pragma unroll
            for (int nj = 0; nj < 4; ++nj) {
                const int n0 = wn * 32 + nj * 8 + g;
                bf[nj][0] = lds_tf32(sw_addr(bB, n0, s * 8 + tg));
                bf[nj][1] = lds_tf32(sw_addr(bB, n0, s * 8 + tg + 4));
            }
            #pragma unroll
            for (int mi = 0; mi < 4; ++mi)
                #pragma unroll
                for (int nj = 0; nj < 4; ++nj)
                    mma_op(acc[mi][nj], af[mi], bf[nj]);
        }
    }

    // epilogue: c0/c1 -> (row, 2tg..2tg+1); c2/c3 -> (row+8, same cols)
    const int bm0 = blockIdx.x * 128, bn0 = blockIdx.y * 128;
    #pragma unroll
    for (int mi = 0; mi < 4; ++mi) {
        const int r0 = bm0 + wm * 64 + mi * 16 + g;
        const float br0 = (bias_mode == 2) ? bias[r0]     : 0.f;
        const float br1 = (bias_mode == 2) ? bias[r0 + 8] : 0.f;
        #pragma unroll
        for (int nj = 0; nj < 4; ++nj) {
            const int col = bn0 + wn * 32 + nj * 8 + 2 * tg;
            float bc0 = 0.f, bc1 = 0.f;
            if (bias_mode == 1) { bc0 = bias[col]; bc1 = bias[col + 1]; }
            float2 v0, v1;
            v0.x = acc[mi][nj][0] * alpha + br0 + bc0;
            v0.y = acc[mi][nj][1] * alpha + br0 + bc1;
            v1.x = acc[mi][nj][2] * alpha + br1 + bc0;
            v1.y = acc[mi][nj][3] * alpha + br1 + bc1;
            *reinterpret_cast<float2*>(C + (size_t)r0 * ldc + col)       = v0;
            *reinterpret_cast<float2*>(C + (size_t)(r0 + 8) * ldc + col) = v1;
        }
    }
}

// ============================================================================
// In-place row softmax over S[8192, 8192]; 1 block/row, 32 elems/thread.
// ============================================================================
__global__ __launch_bounds__(256, 1)
void softmax_kernel(float* __restrict__ S)
{
    __shared__ float red[8];
    __shared__ float bval;
    const int tid = threadIdx.x;
    float* p = S + (size_t)blockIdx.x * M_SEQ;

    float4 v[8];
    float mx = -3.402823466e38f;
    #pragma unroll
    for (int i = 0; i < 8; ++i) {
        v[i] = *reinterpret_cast<const float4*>(p + i * 1024 + tid * 4);
        mx = fmaxf(mx, fmaxf(fmaxf(v[i].x, v[i].y), fmaxf(v[i].z, v[i].w)));
    }
    #pragma unroll
    for (int o = 16; o > 0; o >>= 1)
        mx = fmaxf(mx, __shfl_xor_sync(0xffffffffu, mx, o));
    if ((tid & 31) == 0) red[tid >> 5] = mx;
    __syncthreads();
    if (tid == 0) {
        float m = red[0];
        #pragma unroll
        for (int i = 1; i < 8; ++i) m = fmaxf(m, red[i]);
        bval = m;
    }
    __syncthreads();
    mx = bval;

    const float L2E = 1.4426950408889634f;
    float s = 0.f;
    #pragma unroll
    for (int i = 0; i < 8; ++i) {
        v[i].x = exp2f((v[i].x - mx) * L2E);
        v[i].y = exp2f((v[i].y - mx) * L2E);
        v[i].z = exp2f((v[i].z - mx) * L2E);
        v[i].w = exp2f((v[i].w - mx) * L2E);
        s += (v[i].x + v[i].y) + (v[i].z + v[i].w);
    }
    #pragma unroll
    for (int o = 16; o > 0; o >>= 1)
        s += __shfl_xor_sync(0xffffffffu, s, o);
    __syncthreads();
    if ((tid & 31) == 0) red[tid >> 5] = s;
    __syncthreads();
    if (tid == 0) {
        float t = 0.f;
        #pragma unroll
        for (int i = 0; i < 8; ++i) t += red[i];
        bval = t;
    }
    __syncthreads();
    const float inv = 1.f / bval;

    #pragma unroll
    for (int i = 0; i < 8; ++i) {
        v[i].x *= inv; v[i].y *= inv; v[i].z *= inv; v[i].w *= inv;
        *reinterpret_cast<float4*>(p + i * 1024 + tid * 4) = v[i];
    }
}

extern "C" void kernel_launch(void* const* d_in, const int* in_sizes, int n_in,
                              void* d_out, int out_size)
{
    const float* query = (const float*)d_in[0];
    const float* key   = (const float*)d_in[1];
    const float* value = (const float*)d_in[2];
    const float* Wq    = (const float*)d_in[3];
    const float* bq    = (const float*)d_in[4];
    const float* Wk    = (const float*)d_in[5];
    const float* bk    = (const float*)d_in[6];
    const float* Wv    = (const float*)d_in[7];
    const float* bv    = (const float*)d_in[8];
    float* out = (float*)d_out;

    float *Qp, *Kp, *Vtp, *Sp;
    cudaGetSymbolAddress((void**)&Qp,  g_Q);
    cudaGetSymbolAddress((void**)&Kp,  g_K);
    cudaGetSymbolAddress((void**)&Vtp, g_Vt);
    cudaGetSymbolAddress((void**)&Sp,  g_S);

    cudaFuncSetAttribute(gemm_tf32_kernel,
                         cudaFuncAttributeMaxDynamicSharedMemorySize, SMEM_BYTES);

    // Q = query @ Wq^T + bq            (8192 x 1024)
    gemm_tf32_kernel<<<dim3(64, 8), 256, SMEM_BYTES>>>(
        query, Wq, Qp, bq, 1, 1024, 1024, 1024, 1024, 1.0f);
    // K = key @ Wk^T + bk              (8192 x 1024)
    gemm_tf32_kernel<<<dim3(64, 8), 256, SMEM_BYTES>>>(
        key, Wk, Kp, bk, 1, 1024, 1024, 1024, 1024, 1.0f);
    // Vt = Wv @ value^T + bv[row]      (1024 x 8192), PV-ready layout
    gemm_tf32_kernel<<<dim3(8, 64), 256, SMEM_BYTES>>>(
        Wv, value, Vtp, bv, 2, 1024, 1024, 1024, 8192, 1.0f);
    // S = (Q @ K^T) / 32               (8192 x 8192)
    gemm_tf32_kernel<<<dim3(64, 64), 256, SMEM_BYTES>>>(
        Qp, Kp, Sp, nullptr, 0, 1024, 1024, 1024, 8192, 1.0f / 32.0f);
    // P = softmax rows, in place
    softmax_kernel<<<8192, 256>>>(Sp);
    // O = P @ Vt^T                     (8192 x 1024)
    gemm_tf32_kernel<<<dim3(64, 8), 256, SMEM_BYTES>>>(
        Sp, Vtp, out, nullptr, 0, 8192, 8192, 8192, 1024, 1.0f);
}

// round 7
// speedup vs baseline: 1.1773x; 1.1773x over previous
#include <cuda_runtime.h>
#include <cstdint>
#include <cstddef>

#define N_SEQ 8192
#define M_SEQ 8192
#define D_DIM 1024

__device__ float g_Q [(size_t)N_SEQ * D_DIM];
__device__ float g_K [(size_t)M_SEQ * D_DIM];
__device__ float g_Vt[(size_t)D_DIM * M_SEQ];
__device__ float g_S [(size_t)N_SEQ * M_SEQ];

#define DEV __device__ __forceinline__

DEV uint32_t smem_u32(const void* p) {
    uint32_t a;
    asm("{ .reg .u64 t; cvta.to.shared.u64 t, %1; cvt.u32.u64 %0, t; }"
        : "=r"(a) : "l"(p));
    return a;
}
DEV uint32_t f2t(float x) {   // fp32 -> tf32 RNA; dest must be .b32 reg
    uint32_t y;
    asm("cvt.rna.tf32.f32 %0, %1;" : "=r"(y) : "f"(x));
    return y;
}
DEV float f2tf(float x) {     // rounded value as float (for epilogue stores)
    uint32_t y = f2t(x);
    return __uint_as_float(y);
}
DEV void cp_async16(uint32_t dst, const void* src) {
    asm volatile("cp.async.cg.shared.global [%0], [%1], 16;"
                 :: "r"(dst), "l"(src) : "memory");
}
#define CP_COMMIT() asm volatile("cp.async.commit_group;" ::: "memory")
#define CP_WAIT2()  asm volatile("cp.async.wait_group 2;" ::: "memory")

DEV uint32_t lds_raw(uint32_t a) {
    uint32_t v;
    asm volatile("ld.shared.b32 %0, [%1];" : "=r"(v) : "r"(a));
    return v;
}
DEV uint32_t lds_cvt(uint32_t a) {
    float v;
    asm volatile("ld.shared.b32 %0, [%1];" : "=f"(v) : "r"(a));
    return f2t(v);
}
DEV void mma_op(float* c, const uint32_t* a, const uint32_t* b) {
    asm volatile(
        "mma.sync.aligned.m16n8k8.row.col.f32.tf32.tf32.f32 "
        "{%0,%1,%2,%3}, {%4,%5,%6,%7}, {%8,%9}, {%0,%1,%2,%3};"
        : "+f"(c[0]), "+f"(c[1]), "+f"(c[2]), "+f"(c[3])
        : "r"(a[0]), "r"(a[1]), "r"(a[2]), "r"(a[3]), "r"(b[0]), "r"(b[1]));
}

// ============================================================================
// C[M,N] = alpha * A[M,K] . B[N,K]^T (+bias).  A,B k-major fp32.
// grid = (M/128, N/128), 256 threads, 4-stage cp.async pipeline.
// bias_mode: 0 none, 1 per-column bias[n], 2 per-row bias[m]
// PRE: 1 = operands already tf32-rounded (raw LDS); 0 = CVT in loop
// ROUND_OUT: 1 = round epilogue output to tf32 before store
// ============================================================================
#define STAGES 4
#define SMEM_BYTES (STAGES * 2 * 16384)

template<int PRE, int ROUND_OUT>
__global__ __launch_bounds__(256)
void gemm_tf32_kernel(const float* __restrict__ A, const float* __restrict__ B,
                      float* __restrict__ C, const float* __restrict__ bias,
                      int bias_mode, int K, int lda, int ldb, int ldc, float alpha)
{
    extern __shared__ char smem[];
    const uint32_t sA = smem_u32(smem);
    const uint32_t sB = sA + STAGES * 16384;

    const int tid  = threadIdx.x;
    const int lane = tid & 31, wid = tid >> 5;
    const int g = lane >> 2, tg = lane & 3;
    const int wm = wid & 1, wn = wid >> 1;        // warp tile: 64 x 32

    const float* Ab = A + (size_t)blockIdx.x * 128 * lda;
    const float* Bb = B + (size_t)blockIdx.y * 128 * ldb;
    const int niter = K >> 5;

    const int lr  = tid >> 3;                     // load row 0..31 (+32/pass)
    const int lc4 = tid & 7;                      // float4 col 0..7

    auto issue = [&](int stage, int kc) {
        const uint32_t dA = sA + stage * 16384;
        const uint32_t dB = sB + stage * 16384;
        #pragma unroll
        for (int p = 0; p < 4; ++p) {
            const int row = lr + p * 32;
            const uint32_t so = (uint32_t)(row * 128 + ((lc4 ^ (row & 7)) << 4));
            cp_async16(dA + so, Ab + (size_t)row * lda + kc * 32 + lc4 * 4);
            cp_async16(dB + so, Bb + (size_t)row * ldb + kc * 32 + lc4 * 4);
        }
    };

    issue(0, 0); CP_COMMIT();
    issue(1, 1); CP_COMMIT();
    issue(2, 2); CP_COMMIT();

    // Fragment smem addresses held in registers; advanced by XOR per k-step
    // (chunk index 2s: 0,2,4,6 -> deltas 0x20,0x60,0x20; iter-end ^0x60)
    // and by +16384 per stage (wrap -49152).
    uint32_t ad[24];
    #pragma unroll
    for (int mi = 0; mi < 4; ++mi) {
        const int r0 = wm * 64 + mi * 16 + g;
        #pragma unroll
        for (int q = 0; q < 2; ++q)
            #pragma unroll
            for (int p = 0; p < 2; ++p)
                ad[mi * 4 + q + 2 * p] =
                    sA + (uint32_t)((r0 + q * 8) * 128 + ((p ^ g) << 4) + tg * 4);
    }
    #pragma unroll
    for (int nj = 0; nj < 4; ++nj) {
        const int n0 = wn * 32 + nj * 8 + g;
        #pragma unroll
        for (int p = 0; p < 2; ++p)
            ad[16 + nj * 2 + p] =
                sB + (uint32_t)(n0 * 128 + ((p ^ g) << 4) + tg * 4);
    }

    float acc[4][4][4] = {};

    for (int i = 0; i < niter; ++i) {
        CP_WAIT2();
        __syncthreads();
        if (i + 3 < niter) issue((i + 3) & 3, i + 3);
        CP_COMMIT();

        const uint32_t xadv[4] = {0u, 0x20u, 0x60u, 0x20u};
        #pragma unroll
        for (int s = 0; s < 4; ++s) {
            if (s) {
                #pragma unroll
                for (int t = 0; t < 24; ++t) ad[t] ^= xadv[s];
            }
            uint32_t af[4][4];
            #pragma unroll
            for (int mi = 0; mi < 4; ++mi) {
                #pragma unroll
                for (int j = 0; j < 4; ++j)
                    af[mi][j] = PRE ? lds_raw(ad[mi * 4 + j])
                                    : lds_cvt(ad[mi * 4 + j]);
            }
            uint32_t bf[4][2];
            #pragma unroll
            for (int nj = 0; nj < 4; ++nj) {
                #pragma unroll
                for (int j = 0; j < 2; ++j)
                    bf[nj][j] = PRE ? lds_raw(ad[16 + nj * 2 + j])
                                    : lds_cvt(ad[16 + nj * 2 + j]);
            }
            #pragma unroll
            for (int mi = 0; mi < 4; ++mi)
                #pragma unroll
                for (int nj = 0; nj < 4; ++nj)
                    mma_op(acc[mi][nj], af[mi], bf[nj]);
        }
        const int nxt = ((i & 3) == 3) ? -(3 * 16384) : 16384;
        #pragma unroll
        for (int t = 0; t < 24; ++t) ad[t] = (ad[t] ^ 0x60u) + (uint32_t)nxt;
    }

    // epilogue: c0/c1 -> (row, 2tg..2tg+1); c2/c3 -> (row+8, same cols)
    const int bm0 = blockIdx.x * 128, bn0 = blockIdx.y * 128;
    #pragma unroll
    for (int mi = 0; mi < 4; ++mi) {
        const int r0 = bm0 + wm * 64 + mi * 16 + g;
        const float br0 = (bias_mode == 2) ? bias[r0]     : 0.f;
        const float br1 = (bias_mode == 2) ? bias[r0 + 8] : 0.f;
        #pragma unroll
        for (int nj = 0; nj < 4; ++nj) {
            const int col = bn0 + wn * 32 + nj * 8 + 2 * tg;
            float bc0 = 0.f, bc1 = 0.f;
            if (bias_mode == 1) { bc0 = bias[col]; bc1 = bias[col + 1]; }
            float2 v0, v1;
            v0.x = acc[mi][nj][0] * alpha + br0 + bc0;
            v0.y = acc[mi][nj][1] * alpha + br0 + bc1;
            v1.x = acc[mi][nj][2] * alpha + br1 + bc0;
            v1.y = acc[mi][nj][3] * alpha + br1 + bc1;
            if (ROUND_OUT) {
                v0.x = f2tf(v0.x); v0.y = f2tf(v0.y);
                v1.x = f2tf(v1.x); v1.y = f2tf(v1.y);
            }
            *reinterpret_cast<float2*>(C + (size_t)r0 * ldc + col)       = v0;
            *reinterpret_cast<float2*>(C + (size_t)(r0 + 8) * ldc + col) = v1;
        }
    }
}

// ============================================================================
// In-place row softmax over S[8192, 8192]; 1 block/row, 32 elems/thread.
// Output rounded to tf32 (PV GEMM consumes raw bits).
// ============================================================================
__global__ __launch_bounds__(256, 1)
void softmax_kernel(float* __restrict__ S)
{
    __shared__ float red[8];
    __shared__ float bval;
    const int tid = threadIdx.x;
    float* p = S + (size_t)blockIdx.x * M_SEQ;

    float4 v[8];
    float mx = -3.402823466e38f;
    #pragma unroll
    for (int i = 0; i < 8; ++i) {
        v[i] = *reinterpret_cast<const float4*>(p + i * 1024 + tid * 4);
        mx = fmaxf(mx, fmaxf(fmaxf(v[i].x, v[i].y), fmaxf(v[i].z, v[i].w)));
    }
    #pragma unroll
    for (int o = 16; o > 0; o >>= 1)
        mx = fmaxf(mx, __shfl_xor_sync(0xffffffffu, mx, o));
    if ((tid & 31) == 0) red[tid >> 5] = mx;
    __syncthreads();
    if (tid == 0) {
        float m = red[0];
        #pragma unroll
        for (int i = 1; i < 8; ++i) m = fmaxf(m, red[i]);
        bval = m;
    }
    __syncthreads();
    mx = bval;

    const float L2E = 1.4426950408889634f;
    float s = 0.f;
    #pragma unroll
    for (int i = 0; i < 8; ++i) {
        v[i].x = exp2f((v[i].x - mx) * L2E);
        v[i].y = exp2f((v[i].y - mx) * L2E);
        v[i].z = exp2f((v[i].z - mx) * L2E);
        v[i].w = exp2f((v[i].w - mx) * L2E);
        s += (v[i].x + v[i].y) + (v[i].z + v[i].w);
    }
    #pragma unroll
    for (int o = 16; o > 0; o >>= 1)
        s += __shfl_xor_sync(0xffffffffu, s, o);
    __syncthreads();
    if ((tid & 31) == 0) red[tid >> 5] = s;
    __syncthreads();
    if (tid == 0) {
        float t = 0.f;
        #pragma unroll
        for (int i = 0; i < 8; ++i) t += red[i];
        bval = t;
    }
    __syncthreads();
    const float inv = 1.f / bval;

    #pragma unroll
    for (int i = 0; i < 8; ++i) {
        v[i].x = f2tf(v[i].x * inv);
        v[i].y = f2tf(v[i].y * inv);
        v[i].z = f2tf(v[i].z * inv);
        v[i].w = f2tf(v[i].w * inv);
        *reinterpret_cast<float4*>(p + i * 1024 + tid * 4) = v[i];
    }
}

extern "C" void kernel_launch(void* const* d_in, const int* in_sizes, int n_in,
                              void* d_out, int out_size)
{
    const float* query = (const float*)d_in[0];
    const float* key   = (const float*)d_in[1];
    const float* value = (const float*)d_in[2];
    const float* Wq    = (const float*)d_in[3];
    const float* bq    = (const float*)d_in[4];
    const float* Wk    = (const float*)d_in[5];
    const float* bk    = (const float*)d_in[6];
    const float* Wv    = (const float*)d_in[7];
    const float* bv    = (const float*)d_in[8];
    float* out = (float*)d_out;

    float *Qp, *Kp, *Vtp, *Sp;
    cudaGetSymbolAddress((void**)&Qp,  g_Q);
    cudaGetSymbolAddress((void**)&Kp,  g_K);
    cudaGetSymbolAddress((void**)&Vtp, g_Vt);
    cudaGetSymbolAddress((void**)&Sp,  g_S);

    cudaFuncSetAttribute(gemm_tf32_kernel<0, 1>,
                         cudaFuncAttributeMaxDynamicSharedMemorySize, SMEM_BYTES);
    cudaFuncSetAttribute(gemm_tf32_kernel<1, 0>,
                         cudaFuncAttributeMaxDynamicSharedMemorySize, SMEM_BYTES);

    // Q = query @ Wq^T + bq   (8192x1024), output tf32-rounded
    gemm_tf32_kernel<0, 1><<<dim3(64, 8), 256, SMEM_BYTES>>>(
        query, Wq, Qp, bq, 1, 1024, 1024, 1024, 1024, 1.0f);
    // K = key @ Wk^T + bk     (8192x1024), output tf32-rounded
    gemm_tf32_kernel<0, 1><<<dim3(64, 8), 256, SMEM_BYTES>>>(
        key, Wk, Kp, bk, 1, 1024, 1024, 1024, 1024, 1.0f);
    // Vt = Wv @ value^T + bv[row]  (1024x8192), output tf32-rounded
    gemm_tf32_kernel<0, 1><<<dim3(8, 64), 256, SMEM_BYTES>>>(
        Wv, value, Vtp, bv, 2, 1024, 1024, 1024, 8192, 1.0f);
    // S = (Q @ K^T) / 32      (8192x8192), inputs pre-rounded
    gemm_tf32_kernel<1, 0><<<dim3(64, 64), 256, SMEM_BYTES>>>(
        Qp, Kp, Sp, nullptr, 0, 1024, 1024, 1024, 8192, 1.0f / 32.0f);
    // P = softmax rows, in place; output tf32-rounded
    softmax_kernel<<<8192, 256>>>(Sp);
    // O = P @ Vt^T            (8192x1024), inputs pre-rounded
    gemm_tf32_kernel<1, 0><<<dim3(64, 8), 256, SMEM_BYTES>>>(
        Sp, Vtp, out, nullptr, 0, 8192, 8192, 8192, 1024, 1.0f);
}